// round 12
// baseline (speedup 1.0000x reference)
#include <cuda_runtime.h>
#include <cuda_fp16.h>

// ---------------------------------------------------------------------------
// 3-layer GCN. R12: tcgen05 unavailable (harness targets sm_100, feature-
// gated) -> warp-autonomous mma.sync GEMM instead: W converted once to smem
// (fp16, n-major, conflict-free SK=K+36), each warp owns 16 A-rows and
// streams fragments gmem->reg->MMA with NO barriers in the k-loop.
// R10 evidence: blockwise-synced GEMM was exposed-latency-bound (nothing
// saturated); this removes the block coupling and the whole A smem path.
// Agg + CSR preproc unchanged from R10.
// ---------------------------------------------------------------------------

#define NN 100000
#define NE 1600000
#define IN_C 256
#define H1C 128
#define H2C 64
#define OUTC 32

__device__ int    g_cnt[NN];
__device__ int    g_cursor[NN];
__device__ int    g_off[NN];
__device__ int    g_bsum[128];
__device__ int    g_boff[128];
__device__ float  g_dis[NN];
__device__ int    g_esrc[NE];
__device__ float  g_enorm[NE];
__device__ __half g_h[(size_t)NN * 128];   // GEMM outputs (fp16)
__device__ __half g_a[(size_t)NN * 128];   // agg outputs (fp16, layers 1-2)

// ---------------------------------------------------------------------------
// graph preprocessing (unchanged)
// ---------------------------------------------------------------------------
__global__ void k_zero(int n) {
    int i = blockIdx.x * blockDim.x + threadIdx.x;
    if (i < n) g_cnt[i] = 0;
}
__global__ void k_count(const int* __restrict__ col, int e_cnt) {
    int e = blockIdx.x * blockDim.x + threadIdx.x;
    if (e < e_cnt) atomicAdd(&g_cnt[col[e]], 1);
}
__global__ void k_scan1(int n) {
    __shared__ int s[1024];
    int i = blockIdx.x * 1024 + threadIdx.x;
    int v = (i < n) ? g_cnt[i] : 0;
    if (i < n) g_dis[i] = rsqrtf((float)v + 1.0f);
    s[threadIdx.x] = v;
    __syncthreads();
    #pragma unroll
    for (int off = 1; off < 1024; off <<= 1) {
        int t = (threadIdx.x >= off) ? s[threadIdx.x - off] : 0;
        __syncthreads();
        s[threadIdx.x] += t;
        __syncthreads();
    }
    if (i < n) g_off[i] = s[threadIdx.x];
    if (threadIdx.x == 1023) g_bsum[blockIdx.x] = s[1023];
}
__global__ void k_scan2(int nb) {
    if (blockIdx.x == 0 && threadIdx.x == 0) {
        int run = 0;
        for (int b = 0; b < nb; b++) { g_boff[b] = run; run += g_bsum[b]; }
    }
}
__global__ void k_scan3(int n) {
    int i = blockIdx.x * blockDim.x + threadIdx.x;
    if (i < n) {
        int off = g_off[i] - g_cnt[i] + g_boff[i >> 10];
        g_off[i] = off;
        g_cursor[i] = off;
    }
}
__global__ void k_scatter(const int* __restrict__ row, const int* __restrict__ col, int e_cnt) {
    int e = blockIdx.x * blockDim.x + threadIdx.x;
    if (e >= e_cnt) return;
    int r = row[e], c = col[e];
    int pos = atomicAdd(&g_cursor[c], 1);
    g_esrc[pos]  = r;
    g_enorm[pos] = g_dis[r] * g_dis[c];
}

// ---------------------------------------------------------------------------
// warp-autonomous fp16 GEMM:  C[M,N] = A[M,K] @ W[K,N], fp16 out, fp32 acc.
// W lives in smem (converted once per K-chunk); each warp owns 16 rows,
// streams A fragments straight from gmem. No barriers in the k-loop.
// ---------------------------------------------------------------------------
__device__ __forceinline__ void mma_f16(float* c, const unsigned* a, const unsigned* b) {
    asm volatile(
        "mma.sync.aligned.m16n8k16.row.col.f32.f16.f16.f32 "
        "{%0,%1,%2,%3},{%4,%5,%6,%7},{%8,%9},{%0,%1,%2,%3};"
        : "+f"(c[0]), "+f"(c[1]), "+f"(c[2]), "+f"(c[3])
        : "r"(a[0]), "r"(a[1]), "r"(a[2]), "r"(a[3]), "r"(b[0]), "r"(b[1]));
}

template <typename AT, int N, int K>
__launch_bounds__(256, 2)
__global__ void k_gemmw(const AT* __restrict__ A, const float* __restrict__ W,
                        __half* __restrict__ C, int M) {
    constexpr int CK = (K > 128) ? 128 : K;   // K-chunk (W smem <= 48KB static)
    constexpr int NCHUNK = K / CK;
    constexpr int SK = CK + 36;               // halves; SK/2 % 32 == 18 -> frag loads conflict-free
    constexpr int NT = N / 8;                 // 16 / 8 / 4 acc tiles per warp

    __shared__ __half Ws[N * SK];             // n-major, k-contiguous

    int tid = threadIdx.x;
    int lane = tid & 31, wid = tid >> 5;
    int g = lane >> 2, tg = lane & 3;
    int row0 = (blockIdx.x * 8 + wid) * 16 + g;   // thread's rows: row0, row0+8
    bool ok0 = row0 < M, ok1 = (row0 + 8) < M;

    float acc[NT][4] = {};

    for (int ch = 0; ch < NCHUNK; ch++) {
        int kbase = ch * CK;
        if (ch) __syncthreads();              // Ws reuse guard
        // ---- fill Ws: coalesced reads over n, half2 stores ----
        constexpr int UNITS = (CK / 2) * N;
        #pragma unroll
        for (int i = 0; i < UNITS / 256; i++) {
            int u = tid + i * 256;
            int kp = u / N, n = u % N;
            int k = kbase + 2 * kp;
            float w0 = W[(size_t)k * N + n];
            float w1 = W[(size_t)(k + 1) * N + n];
            *reinterpret_cast<__half2*>(Ws + n * SK + 2 * kp) = __floats2half2_rn(w0, w1);
        }
        __syncthreads();

        // ---- barrier-free mainloop: stream A fragments, MMA ----
        #pragma unroll
        for (int kk = 0; kk < CK; kk += 16) {
            int k = kbase + kk + 2 * tg;
            unsigned a[4];
            if constexpr (sizeof(AT) == 4) {
                const float* Af = reinterpret_cast<const float*>(A);
                float2 f0 = ok0 ? *reinterpret_cast<const float2*>(Af + (size_t)row0 * K + k)
                                : make_float2(0.f, 0.f);
                float2 f1 = ok1 ? *reinterpret_cast<const float2*>(Af + (size_t)(row0 + 8) * K + k)
                                : make_float2(0.f, 0.f);
                float2 f2 = ok0 ? *reinterpret_cast<const float2*>(Af + (size_t)row0 * K + k + 8)
                                : make_float2(0.f, 0.f);
                float2 f3 = ok1 ? *reinterpret_cast<const float2*>(Af + (size_t)(row0 + 8) * K + k + 8)
                                : make_float2(0.f, 0.f);
                __half2 h0 = __floats2half2_rn(f0.x, f0.y);
                __half2 h1 = __floats2half2_rn(f1.x, f1.y);
                __half2 h2 = __floats2half2_rn(f2.x, f2.y);
                __half2 h3 = __floats2half2_rn(f3.x, f3.y);
                a[0] = *reinterpret_cast<unsigned*>(&h0);
                a[1] = *reinterpret_cast<unsigned*>(&h1);
                a[2] = *reinterpret_cast<unsigned*>(&h2);
                a[3] = *reinterpret_cast<unsigned*>(&h3);
            } else {
                const __half* Ah = reinterpret_cast<const __half*>(A);
                a[0] = ok0 ? *reinterpret_cast<const unsigned*>(Ah + (size_t)row0 * K + k) : 0u;
                a[1] = ok1 ? *reinterpret_cast<const unsigned*>(Ah + (size_t)(row0 + 8) * K + k) : 0u;
                a[2] = ok0 ? *reinterpret_cast<const unsigned*>(Ah + (size_t)row0 * K + k + 8) : 0u;
                a[3] = ok1 ? *reinterpret_cast<const unsigned*>(Ah + (size_t)(row0 + 8) * K + k + 8) : 0u;
            }
            #pragma unroll
            for (int nt = 0; nt < NT; nt++) {
                const __half* bp = Ws + (nt * 8 + g) * SK + kk + 2 * tg;
                unsigned b[2];
                b[0] = *reinterpret_cast<const unsigned*>(bp);
                b[1] = *reinterpret_cast<const unsigned*>(bp + 8);
                mma_f16(acc[nt], a, b);
            }
        }
    }

    // ---- epilogue: fp16 stores ----
    #pragma unroll
    for (int nt = 0; nt < NT; nt++) {
        int col = nt * 8 + 2 * tg;
        if (ok0)
            *reinterpret_cast<__half2*>(C + (size_t)row0 * N + col) =
                __floats2half2_rn(acc[nt][0], acc[nt][1]);
        if (ok1)
            *reinterpret_cast<__half2*>(C + (size_t)(row0 + 8) * N + col) =
                __floats2half2_rn(acc[nt][2], acc[nt][3]);
    }
}

// ---------------------------------------------------------------------------
// aggregation (unchanged from R10)
// ---------------------------------------------------------------------------
template <int VEC>
__device__ __forceinline__ void loadh(float* d, const __half* __restrict__ p) {
    if constexpr (VEC == 4) {
        uint2 raw = __ldg(reinterpret_cast<const uint2*>(p));
        float2 a = __half22float2(*reinterpret_cast<const __half2*>(&raw.x));
        float2 b = __half22float2(*reinterpret_cast<const __half2*>(&raw.y));
        d[0] = a.x; d[1] = a.y; d[2] = b.x; d[3] = b.y;
    } else if constexpr (VEC == 2) {
        __half2 h2 = __ldg(reinterpret_cast<const __half2*>(p));
        float2 a = __half22float2(h2);
        d[0] = a.x; d[1] = a.y;
    } else {
        d[0] = __half2float(__ldg(p));
    }
}

template <int F, bool RELU, typename OutT>
__launch_bounds__(256)
__global__ void k_agg(const __half* __restrict__ h, const float* __restrict__ bias,
                      OutT* __restrict__ out) {
    constexpr int VEC = F / 32;
    int node = (blockIdx.x * blockDim.x + threadIdx.x) >> 5;
    int lane = threadIdx.x & 31;
    if (node >= NN) return;

    float acc[VEC];
    {
        float d = g_dis[node];
        float ns = d * d;
        float t[VEC];
        loadh<VEC>(t, h + (size_t)node * F + lane * VEC);
        #pragma unroll
        for (int v = 0; v < VEC; v++) acc[v] = ns * t[v];
    }

    int start = g_off[node];
    int cnt   = g_cnt[node];
    int e = start, end = start + cnt;

    for (; e + 8 <= end; e += 8) {
        int   s[8];
        float nm[8];
        #pragma unroll
        for (int j = 0; j < 8; j++) { s[j] = g_esrc[e + j]; nm[j] = g_enorm[e + j]; }
        float t[8][VEC];
        #pragma unroll
        for (int j = 0; j < 8; j++)
            loadh<VEC>(t[j], h + (size_t)s[j] * F + lane * VEC);
        #pragma unroll
        for (int j = 0; j < 8; j++)
            #pragma unroll
            for (int v = 0; v < VEC; v++) acc[v] += nm[j] * t[j][v];
    }
    for (; e + 4 <= end; e += 4) {
        int   s[4];
        float nm[4];
        #pragma unroll
        for (int j = 0; j < 4; j++) { s[j] = g_esrc[e + j]; nm[j] = g_enorm[e + j]; }
        float t[4][VEC];
        #pragma unroll
        for (int j = 0; j < 4; j++)
            loadh<VEC>(t[j], h + (size_t)s[j] * F + lane * VEC);
        #pragma unroll
        for (int j = 0; j < 4; j++)
            #pragma unroll
            for (int v = 0; v < VEC; v++) acc[v] += nm[j] * t[j][v];
    }
    for (; e < end; e++) {
        int s0 = g_esrc[e];
        float nm = g_enorm[e];
        float t[VEC];
        loadh<VEC>(t, h + (size_t)s0 * F + lane * VEC);
        #pragma unroll
        for (int v = 0; v < VEC; v++) acc[v] += nm * t[v];
    }

    float res[VEC];
    #pragma unroll
    for (int v = 0; v < VEC; v++) {
        float r = acc[v] + bias[lane * VEC + v];
        if (RELU) r = fmaxf(r, 0.0f);
        res[v] = r;
    }

    if constexpr (sizeof(OutT) == 2) {
        __half* op = reinterpret_cast<__half*>(out) + (size_t)node * F + lane * VEC;
        if constexpr (VEC == 4) {
            __half2 p0 = __floats2half2_rn(res[0], res[1]);
            __half2 p1 = __floats2half2_rn(res[2], res[3]);
            *reinterpret_cast<uint2*>(op) =
                make_uint2(*reinterpret_cast<unsigned*>(&p0), *reinterpret_cast<unsigned*>(&p1));
        } else if constexpr (VEC == 2) {
            *reinterpret_cast<__half2*>(op) = __floats2half2_rn(res[0], res[1]);
        } else {
            *op = __float2half_rn(res[0]);
        }
    } else {
        float* op = reinterpret_cast<float*>(out) + (size_t)node * F + lane * VEC;
        if constexpr (VEC == 4)
            *reinterpret_cast<float4*>(op) = make_float4(res[0], res[1], res[2], res[3]);
        else if constexpr (VEC == 2)
            *reinterpret_cast<float2*>(op) = make_float2(res[0], res[1]);
        else
            *op = res[0];
    }
}

// ---------------------------------------------------------------------------
extern "C" void kernel_launch(void* const* d_in, const int* in_sizes, int n_in,
                              void* d_out, int out_size) {
    const float* x  = (const float*)d_in[0];
    const int*   ei = (const int*)d_in[1];
    const float* W1 = (const float*)d_in[2];
    const float* b1 = (const float*)d_in[3];
    const float* W2 = (const float*)d_in[4];
    const float* b2 = (const float*)d_in[5];
    const float* W3 = (const float*)d_in[6];
    const float* b3 = (const float*)d_in[7];

    int M = in_sizes[0] / IN_C;   // 100000
    int E = in_sizes[1] / 2;      // 1600000
    const int* row = ei;          // sources
    const int* col = ei + E;      // targets
    float* out = (float*)d_out;

    __half *gh, *ga;
    cudaGetSymbolAddress((void**)&gh, g_h);
    cudaGetSymbolAddress((void**)&ga, g_a);

    int nb1024 = (M + 1023) / 1024;
    int aggBlocks = (M + 7) / 8;
    int gemmBlocks = (M + 127) / 128;   // 128 rows per block (8 warps x 16)

    // gemm1 kept in launch slot 4 for the ncu window
    k_zero   <<<(M + 255) / 256, 256>>>(M);                            // 1
    k_count  <<<(E + 255) / 256, 256>>>(col, E);                       // 2
    k_scan1  <<<nb1024, 1024>>>(M);                                    // 3
    k_gemmw<float, H1C, IN_C><<<gemmBlocks, 256>>>(x, W1, gh, M);      // 4 <- profiled
    k_scan2  <<<1, 32>>>(nb1024);                                      // 5
    k_scan3  <<<(M + 255) / 256, 256>>>(M);                            // 6
    k_scatter<<<(E + 255) / 256, 256>>>(row, col, E);                  // 7

    k_agg<H1C, true, __half><<<aggBlocks, 256>>>(gh, b1, ga);

    k_gemmw<__half, H2C, H1C><<<gemmBlocks, 256>>>(ga, W2, gh, M);
    k_agg<H2C, true, __half><<<aggBlocks, 256>>>(gh, b2, ga);

    k_gemmw<__half, OUTC, H2C><<<gemmBlocks, 256>>>(ga, W3, gh, M);
    k_agg<OUTC, false, float><<<aggBlocks, 256>>>(gh, b3, out);
}

// round 13
// speedup vs baseline: 1.0645x; 1.0645x over previous
#include <cuda_runtime.h>
#include <cuda_fp16.h>

// ---------------------------------------------------------------------------
// 3-layer GCN. R13: revert GEMM to R10 (best: 270.4us; R12 warp-autonomous
// layout was uncoalesced and regressed). New: fork the capture stream with
// events so the CSR-preproc chain runs CONCURRENTLY with gemm1 (independent
// until agg1) -- two-branch CUDA graph, ~35us of preproc hidden under the
// latency-bound gemm1 (issue 20%, plenty of idle slots).
// ---------------------------------------------------------------------------

#define NN 100000
#define NE 1600000
#define IN_C 256
#define H1C 128
#define H2C 64
#define OUTC 32

__device__ int    g_cnt[NN];
__device__ int    g_cursor[NN];
__device__ int    g_off[NN];
__device__ int    g_bsum[128];
__device__ int    g_boff[128];
__device__ float  g_dis[NN];
__device__ int    g_esrc[NE];
__device__ float  g_enorm[NE];
__device__ __half g_h[(size_t)NN * 128];   // GEMM outputs (fp16)
__device__ __half g_a[(size_t)NN * 128];   // agg outputs (fp16, layers 1-2)

// ---------------------------------------------------------------------------
// graph preprocessing
// ---------------------------------------------------------------------------
__global__ void k_zero(int n) {
    int i = blockIdx.x * blockDim.x + threadIdx.x;
    if (i < n) g_cnt[i] = 0;
}
__global__ void k_count(const int* __restrict__ col, int e_cnt) {
    int e = blockIdx.x * blockDim.x + threadIdx.x;
    if (e < e_cnt) atomicAdd(&g_cnt[col[e]], 1);
}
__global__ void k_scan1(int n) {
    __shared__ int s[1024];
    int i = blockIdx.x * 1024 + threadIdx.x;
    int v = (i < n) ? g_cnt[i] : 0;
    if (i < n) g_dis[i] = rsqrtf((float)v + 1.0f);
    s[threadIdx.x] = v;
    __syncthreads();
    #pragma unroll
    for (int off = 1; off < 1024; off <<= 1) {
        int t = (threadIdx.x >= off) ? s[threadIdx.x - off] : 0;
        __syncthreads();
        s[threadIdx.x] += t;
        __syncthreads();
    }
    if (i < n) g_off[i] = s[threadIdx.x];
    if (threadIdx.x == 1023) g_bsum[blockIdx.x] = s[1023];
}
__global__ void k_scan2(int nb) {
    if (blockIdx.x == 0 && threadIdx.x == 0) {
        int run = 0;
        for (int b = 0; b < nb; b++) { g_boff[b] = run; run += g_bsum[b]; }
    }
}
__global__ void k_scan3(int n) {
    int i = blockIdx.x * blockDim.x + threadIdx.x;
    if (i < n) {
        int off = g_off[i] - g_cnt[i] + g_boff[i >> 10];
        g_off[i] = off;
        g_cursor[i] = off;
    }
}
__global__ void k_scatter(const int* __restrict__ row, const int* __restrict__ col, int e_cnt) {
    int e = blockIdx.x * blockDim.x + threadIdx.x;
    if (e >= e_cnt) return;
    int r = row[e], c = col[e];
    int pos = atomicAdd(&g_cursor[c], 1);
    g_esrc[pos]  = r;
    g_enorm[pos] = g_dis[r] * g_dis[c];
}

// ---------------------------------------------------------------------------
// fp16 GEMM (R10 structure): C[M,N] = A[M,K] @ W[K,N], fp16 out, fp32 acc
// ---------------------------------------------------------------------------
__device__ __forceinline__ void mma_f16(float* c, const unsigned* a, const unsigned* b) {
    asm volatile(
        "mma.sync.aligned.m16n8k16.row.col.f32.f16.f16.f32 "
        "{%0,%1,%2,%3},{%4,%5,%6,%7},{%8,%9},{%0,%1,%2,%3};"
        : "+f"(c[0]), "+f"(c[1]), "+f"(c[2]), "+f"(c[3])
        : "r"(a[0]), "r"(a[1]), "r"(a[2]), "r"(a[3]), "r"(b[0]), "r"(b[1]));
}

template <typename AT, int N, int K>
__launch_bounds__(256, 2)
__global__ void k_gemm(const AT* __restrict__ A, const float* __restrict__ W,
                       __half* __restrict__ C, int M) {
    constexpr bool A16 = (sizeof(AT) == 2);
    constexpr int BM = 64, BK = 32;
    constexpr int SA = BK + 8;         // 40 halves: conflict-free frag loads
    constexpr int SW = BK + 4;         // 36 halves: conflict-free half2 stores
    constexpr int WM = 32;
    constexpr int WN = N / 4;          // 32 / 16 / 8
    constexpr int MT = 2;
    constexpr int NT = WN / 8;         // 4 / 2 / 1
    constexpr int KSTEP = 256 / N;
    constexpr int WITER = (BK / 2) / KSTEP;

    __shared__ __half As[BM * SA];
    __shared__ __half Ws[N * SW];      // n-major, k-contiguous

    int tid = threadIdx.x;
    int lane = tid & 31, warp = tid >> 5;
    int wm = (warp & 1) * WM;
    int wn = (warp >> 1) * WN;
    int m0 = blockIdx.x * BM;
    int g = lane >> 2, tg = lane & 3;

    float acc[MT][NT][4] = {};

    int a_r[2], a_c[2];
    #pragma unroll
    for (int i = 0; i < 2; i++) {
        int idx = tid + i * 256;
        a_r[i] = idx >> 3;
        a_c[i] = idx & 7;
    }
    int n_w = tid % N;
    int k2b = tid / N;

    float4 aRegF[2];
    uint2  aRegH[2];
    float2 wReg[WITER];

    #pragma unroll
    for (int i = 0; i < 2; i++) {
        int m = m0 + a_r[i];
        if (A16) {
            aRegH[i] = make_uint2(0u, 0u);
            if (m < M)
                aRegH[i] = *reinterpret_cast<const uint2*>(
                    reinterpret_cast<const __half*>(A) + (size_t)m * K + a_c[i] * 4);
        } else {
            aRegF[i] = make_float4(0.f, 0.f, 0.f, 0.f);
            if (m < M)
                aRegF[i] = *reinterpret_cast<const float4*>(
                    reinterpret_cast<const float*>(A) + (size_t)m * K + a_c[i] * 4);
        }
    }
    #pragma unroll
    for (int i = 0; i < WITER; i++) {
        int k = 2 * (k2b + i * KSTEP);
        wReg[i] = make_float2(W[(size_t)k * N + n_w], W[(size_t)(k + 1) * N + n_w]);
    }

    for (int k0 = 0; k0 < K; k0 += BK) {
        #pragma unroll
        for (int i = 0; i < 2; i++) {
            uint2 u;
            if (A16) {
                u = aRegH[i];
            } else {
                __half2 p0 = __floats2half2_rn(aRegF[i].x, aRegF[i].y);
                __half2 p1 = __floats2half2_rn(aRegF[i].z, aRegF[i].w);
                u = make_uint2(*reinterpret_cast<unsigned*>(&p0),
                               *reinterpret_cast<unsigned*>(&p1));
            }
            *reinterpret_cast<uint2*>(As + a_r[i] * SA + a_c[i] * 4) = u;
        }
        #pragma unroll
        for (int i = 0; i < WITER; i++) {
            int k2 = k2b + i * KSTEP;
            *reinterpret_cast<__half2*>(Ws + n_w * SW + 2 * k2) =
                __floats2half2_rn(wReg[i].x, wReg[i].y);
        }
        __syncthreads();

        int kn = k0 + BK;
        if (kn < K) {
            #pragma unroll
            for (int i = 0; i < 2; i++) {
                int m = m0 + a_r[i];
                if (A16) {
                    aRegH[i] = make_uint2(0u, 0u);
                    if (m < M)
                        aRegH[i] = *reinterpret_cast<const uint2*>(
                            reinterpret_cast<const __half*>(A) + (size_t)m * K + kn + a_c[i] * 4);
                } else {
                    aRegF[i] = make_float4(0.f, 0.f, 0.f, 0.f);
                    if (m < M)
                        aRegF[i] = *reinterpret_cast<const float4*>(
                            reinterpret_cast<const float*>(A) + (size_t)m * K + kn + a_c[i] * 4);
                }
            }
            #pragma unroll
            for (int i = 0; i < WITER; i++) {
                int k = kn + 2 * (k2b + i * KSTEP);
                wReg[i] = make_float2(W[(size_t)k * N + n_w], W[(size_t)(k + 1) * N + n_w]);
            }
        }

        #pragma unroll
        for (int kk = 0; kk < BK; kk += 16) {
            unsigned a[MT][4];
            #pragma unroll
            for (int mt = 0; mt < MT; mt++) {
                int base = (wm + mt * 16 + g) * SA + kk + tg * 2;
                a[mt][0] = *reinterpret_cast<const unsigned*>(As + base);
                a[mt][1] = *reinterpret_cast<const unsigned*>(As + base + 8 * SA);
                a[mt][2] = *reinterpret_cast<const unsigned*>(As + base + 8);
                a[mt][3] = *reinterpret_cast<const unsigned*>(As + base + 8 * SA + 8);
            }
            #pragma unroll
            for (int nt = 0; nt < NT; nt++) {
                int bb = (wn + nt * 8 + g) * SW + kk + tg * 2;
                unsigned b[2];
                b[0] = *reinterpret_cast<const unsigned*>(Ws + bb);
                b[1] = *reinterpret_cast<const unsigned*>(Ws + bb + 8);
                #pragma unroll
                for (int mt = 0; mt < MT; mt++)
                    mma_f16(acc[mt][nt], a[mt], b);
            }
        }
        __syncthreads();
    }

    #pragma unroll
    for (int mt = 0; mt < MT; mt++) {
        #pragma unroll
        for (int nt = 0; nt < NT; nt++) {
            int row0 = m0 + wm + mt * 16 + g;
            int col = wn + nt * 8 + 2 * tg;
            if (row0 < M)
                *reinterpret_cast<__half2*>(C + (size_t)row0 * N + col) =
                    __floats2half2_rn(acc[mt][nt][0], acc[mt][nt][1]);
            int row1 = row0 + 8;
            if (row1 < M)
                *reinterpret_cast<__half2*>(C + (size_t)row1 * N + col) =
                    __floats2half2_rn(acc[mt][nt][2], acc[mt][nt][3]);
        }
    }
}

// ---------------------------------------------------------------------------
// aggregation: warp per node; fp16 gathers, fp32 accumulate, OutT output
// ---------------------------------------------------------------------------
template <int VEC>
__device__ __forceinline__ void loadh(float* d, const __half* __restrict__ p) {
    if constexpr (VEC == 4) {
        uint2 raw = __ldg(reinterpret_cast<const uint2*>(p));
        float2 a = __half22float2(*reinterpret_cast<const __half2*>(&raw.x));
        float2 b = __half22float2(*reinterpret_cast<const __half2*>(&raw.y));
        d[0] = a.x; d[1] = a.y; d[2] = b.x; d[3] = b.y;
    } else if constexpr (VEC == 2) {
        __half2 h2 = __ldg(reinterpret_cast<const __half2*>(p));
        float2 a = __half22float2(h2);
        d[0] = a.x; d[1] = a.y;
    } else {
        d[0] = __half2float(__ldg(p));
    }
}

template <int F, bool RELU, typename OutT>
__launch_bounds__(256)
__global__ void k_agg(const __half* __restrict__ h, const float* __restrict__ bias,
                      OutT* __restrict__ out) {
    constexpr int VEC = F / 32;
    int node = (blockIdx.x * blockDim.x + threadIdx.x) >> 5;
    int lane = threadIdx.x & 31;
    if (node >= NN) return;

    float acc[VEC];
    {
        float d = g_dis[node];
        float ns = d * d;
        float t[VEC];
        loadh<VEC>(t, h + (size_t)node * F + lane * VEC);
        #pragma unroll
        for (int v = 0; v < VEC; v++) acc[v] = ns * t[v];
    }

    int start = g_off[node];
    int cnt   = g_cnt[node];
    int e = start, end = start + cnt;

    for (; e + 8 <= end; e += 8) {
        int   s[8];
        float nm[8];
        #pragma unroll
        for (int j = 0; j < 8; j++) { s[j] = g_esrc[e + j]; nm[j] = g_enorm[e + j]; }
        float t[8][VEC];
        #pragma unroll
        for (int j = 0; j < 8; j++)
            loadh<VEC>(t[j], h + (size_t)s[j] * F + lane * VEC);
        #pragma unroll
        for (int j = 0; j < 8; j++)
            #pragma unroll
            for (int v = 0; v < VEC; v++) acc[v] += nm[j] * t[j][v];
    }
    for (; e + 4 <= end; e += 4) {
        int   s[4];
        float nm[4];
        #pragma unroll
        for (int j = 0; j < 4; j++) { s[j] = g_esrc[e + j]; nm[j] = g_enorm[e + j]; }
        float t[4][VEC];
        #pragma unroll
        for (int j = 0; j < 4; j++)
            loadh<VEC>(t[j], h + (size_t)s[j] * F + lane * VEC);
        #pragma unroll
        for (int j = 0; j < 4; j++)
            #pragma unroll
            for (int v = 0; v < VEC; v++) acc[v] += nm[j] * t[j][v];
    }
    for (; e < end; e++) {
        int s0 = g_esrc[e];
        float nm = g_enorm[e];
        float t[VEC];
        loadh<VEC>(t, h + (size_t)s0 * F + lane * VEC);
        #pragma unroll
        for (int v = 0; v < VEC; v++) acc[v] += nm * t[v];
    }

    float res[VEC];
    #pragma unroll
    for (int v = 0; v < VEC; v++) {
        float r = acc[v] + bias[lane * VEC + v];
        if (RELU) r = fmaxf(r, 0.0f);
        res[v] = r;
    }

    if constexpr (sizeof(OutT) == 2) {
        __half* op = reinterpret_cast<__half*>(out) + (size_t)node * F + lane * VEC;
        if constexpr (VEC == 4) {
            __half2 p0 = __floats2half2_rn(res[0], res[1]);
            __half2 p1 = __floats2half2_rn(res[2], res[3]);
            *reinterpret_cast<uint2*>(op) =
                make_uint2(*reinterpret_cast<unsigned*>(&p0), *reinterpret_cast<unsigned*>(&p1));
        } else if constexpr (VEC == 2) {
            *reinterpret_cast<__half2*>(op) = __floats2half2_rn(res[0], res[1]);
        } else {
            *op = __float2half_rn(res[0]);
        }
    } else {
        float* op = reinterpret_cast<float*>(out) + (size_t)node * F + lane * VEC;
        if constexpr (VEC == 4)
            *reinterpret_cast<float4*>(op) = make_float4(res[0], res[1], res[2], res[3]);
        else if constexpr (VEC == 2)
            *reinterpret_cast<float2*>(op) = make_float2(res[0], res[1]);
        else
            *op = res[0];
    }
}

// ---------------------------------------------------------------------------
extern "C" void kernel_launch(void* const* d_in, const int* in_sizes, int n_in,
                              void* d_out, int out_size) {
    const float* x  = (const float*)d_in[0];
    const int*   ei = (const int*)d_in[1];
    const float* W1 = (const float*)d_in[2];
    const float* b1 = (const float*)d_in[3];
    const float* W2 = (const float*)d_in[4];
    const float* b2 = (const float*)d_in[5];
    const float* W3 = (const float*)d_in[6];
    const float* b3 = (const float*)d_in[7];

    int M = in_sizes[0] / IN_C;   // 100000
    int E = in_sizes[1] / 2;      // 1600000
    const int* row = ei;          // sources
    const int* col = ei + E;      // targets
    float* out = (float*)d_out;

    __half *gh, *ga;
    cudaGetSymbolAddress((void**)&gh, g_h);
    cudaGetSymbolAddress((void**)&ga, g_a);

    // side stream + fork/join events (host objects; created once; GPU work
    // per call is identical and fully captured via event fork/join)
    static cudaStream_t s2 = nullptr;
    static cudaEvent_t evFork = nullptr, evJoin = nullptr;
    if (s2 == nullptr) {
        cudaStreamCreateWithFlags(&s2, cudaStreamNonBlocking);
        cudaEventCreateWithFlags(&evFork, cudaEventDisableTiming);
        cudaEventCreateWithFlags(&evJoin, cudaEventDisableTiming);
    }

    int nb1024 = (M + 1023) / 1024;
    int aggBlocks = (M + 7) / 8;
    int gemmBlocks = (M + 63) / 64;

    // ---- fork: CSR preproc chain on s2, gemm1 on main stream ----
    cudaEventRecord(evFork, 0);
    cudaStreamWaitEvent(s2, evFork, 0);

    k_zero   <<<(M + 255) / 256, 256, 0, s2>>>(M);
    k_count  <<<(E + 255) / 256, 256, 0, s2>>>(col, E);
    k_scan1  <<<nb1024, 1024, 0, s2>>>(M);
    k_scan2  <<<1, 32, 0, s2>>>(nb1024);
    k_scan3  <<<(M + 255) / 256, 256, 0, s2>>>(M);
    k_scatter<<<(E + 255) / 256, 256, 0, s2>>>(row, col, E);
    cudaEventRecord(evJoin, s2);

    k_gemm<float, H1C, IN_C><<<gemmBlocks, 256>>>(x, W1, gh, M);   // concurrent with preproc

    // ---- join: agg1 needs both branches ----
    cudaStreamWaitEvent(0, evJoin, 0);

    k_agg<H1C, true, __half><<<aggBlocks, 256>>>(gh, b1, ga);

    k_gemm<__half, H2C, H1C><<<gemmBlocks, 256>>>(ga, W2, gh, M);
    k_agg<H2C, true, __half><<<aggBlocks, 256>>>(gh, b2, ga);

    k_gemm<__half, OUTC, H2C><<<gemmBlocks, 256>>>(ga, W3, gh, M);
    k_agg<OUTC, false, float><<<aggBlocks, 256>>>(gh, b3, out);
}

// round 14
// speedup vs baseline: 1.1272x; 1.0589x over previous
#include <cuda_runtime.h>
#include <cuda_fp16.h>

// ---------------------------------------------------------------------------
// 3-layer GCN. R14: (a) GEMM gets double-buffered smem (1 barrier/tile) with
// 2-tile-ahead A prefetch (2x DRAM MLP; R10 profile showed gemm1 streaming A
// at only 1.7TB/s, latency-limited); (b) k_scan2 parallelized (was 9.1us
// serial, nearly co-critical with shortened gemm1 in the forked region).
// Stream fork (R13, -8.8us) and all other structure retained.
// ---------------------------------------------------------------------------

#define NN 100000
#define NE 1600000
#define IN_C 256
#define H1C 128
#define H2C 64
#define OUTC 32

__device__ int    g_cnt[NN];
__device__ int    g_cursor[NN];
__device__ int    g_off[NN];
__device__ int    g_bsum[128];
__device__ int    g_boff[128];
__device__ float  g_dis[NN];
__device__ int    g_esrc[NE];
__device__ float  g_enorm[NE];
__device__ __half g_h[(size_t)NN * 128];   // GEMM outputs (fp16)
__device__ __half g_a[(size_t)NN * 128];   // agg outputs (fp16, layers 1-2)

// ---------------------------------------------------------------------------
// graph preprocessing
// ---------------------------------------------------------------------------
__global__ void k_zero(int n) {
    int i = blockIdx.x * blockDim.x + threadIdx.x;
    if (i < n) g_cnt[i] = 0;
}
__global__ void k_count(const int* __restrict__ col, int e_cnt) {
    int e = blockIdx.x * blockDim.x + threadIdx.x;
    if (e < e_cnt) atomicAdd(&g_cnt[col[e]], 1);
}
__global__ void k_scan1(int n) {
    __shared__ int s[1024];
    int i = blockIdx.x * 1024 + threadIdx.x;
    int v = (i < n) ? g_cnt[i] : 0;
    if (i < n) g_dis[i] = rsqrtf((float)v + 1.0f);
    s[threadIdx.x] = v;
    __syncthreads();
    #pragma unroll
    for (int off = 1; off < 1024; off <<= 1) {
        int t = (threadIdx.x >= off) ? s[threadIdx.x - off] : 0;
        __syncthreads();
        s[threadIdx.x] += t;
        __syncthreads();
    }
    if (i < n) g_off[i] = s[threadIdx.x];
    if (threadIdx.x == 1023) g_bsum[blockIdx.x] = s[1023];
}
// parallel exclusive scan of block sums (nb <= 128)
__global__ void k_scan2(int nb) {
    __shared__ int s[128];
    int t = threadIdx.x;
    int v = (t < nb) ? g_bsum[t] : 0;
    s[t] = v;
    __syncthreads();
    #pragma unroll
    for (int off = 1; off < 128; off <<= 1) {
        int u = (t >= off) ? s[t - off] : 0;
        __syncthreads();
        s[t] += u;
        __syncthreads();
    }
    if (t < nb) g_boff[t] = s[t] - v;   // exclusive
}
__global__ void k_scan3(int n) {
    int i = blockIdx.x * blockDim.x + threadIdx.x;
    if (i < n) {
        int off = g_off[i] - g_cnt[i] + g_boff[i >> 10];
        g_off[i] = off;
        g_cursor[i] = off;
    }
}
__global__ void k_scatter(const int* __restrict__ row, const int* __restrict__ col, int e_cnt) {
    int e = blockIdx.x * blockDim.x + threadIdx.x;
    if (e >= e_cnt) return;
    int r = row[e], c = col[e];
    int pos = atomicAdd(&g_cursor[c], 1);
    g_esrc[pos]  = r;
    g_enorm[pos] = g_dis[r] * g_dis[c];
}

// ---------------------------------------------------------------------------
// fp16 GEMM, double-buffered smem, 2-tile A lookahead
// ---------------------------------------------------------------------------
__device__ __forceinline__ void mma_f16(float* c, const unsigned* a, const unsigned* b) {
    asm volatile(
        "mma.sync.aligned.m16n8k16.row.col.f32.f16.f16.f32 "
        "{%0,%1,%2,%3},{%4,%5,%6,%7},{%8,%9},{%0,%1,%2,%3};"
        : "+f"(c[0]), "+f"(c[1]), "+f"(c[2]), "+f"(c[3])
        : "r"(a[0]), "r"(a[1]), "r"(a[2]), "r"(a[3]), "r"(b[0]), "r"(b[1]));
}

template <typename AT, int N, int K>
__launch_bounds__(256, 2)
__global__ void k_gemm(const AT* __restrict__ A, const float* __restrict__ W,
                       __half* __restrict__ C, int M) {
    constexpr bool A16 = (sizeof(AT) == 2);
    constexpr int BM = 64, BK = 32;
    constexpr int SA = BK + 8;         // 40 halves
    constexpr int SW = BK + 4;         // 36 halves
    constexpr int WM = 32;
    constexpr int WN = N / 4;
    constexpr int MT = 2;
    constexpr int NT = WN / 8;
    constexpr int KSTEP = 256 / N;
    constexpr int WITER = (BK / 2) / KSTEP;
    constexpr int ABUF = BM * SA;
    constexpr int WBUF = N * SW;

    __shared__ __half As[2 * ABUF];
    __shared__ __half Ws[2 * WBUF];

    int tid = threadIdx.x;
    int lane = tid & 31, warp = tid >> 5;
    int wm = (warp & 1) * WM;
    int wn = (warp >> 1) * WN;
    int m0 = blockIdx.x * BM;
    int g = lane >> 2, tg = lane & 3;

    float acc[MT][NT][4] = {};

    int a_r[2], a_c[2];
    #pragma unroll
    for (int i = 0; i < 2; i++) {
        int idx = tid + i * 256;
        a_r[i] = idx >> 3;
        a_c[i] = idx & 7;
    }
    int n_w = tid % N;
    int k2b = tid / N;

    float4 aRegF[2];
    uint2  aRegH[2];
    float2 wReg[WITER];

    bool arow_ok[2];
    #pragma unroll
    for (int i = 0; i < 2; i++) arow_ok[i] = (m0 + a_r[i]) < M;

    auto loadA = [&](int kb) {
        #pragma unroll
        for (int i = 0; i < 2; i++) {
            int m = m0 + a_r[i];
            if (A16) {
                aRegH[i] = make_uint2(0u, 0u);
                if (arow_ok[i])
                    aRegH[i] = *reinterpret_cast<const uint2*>(
                        reinterpret_cast<const __half*>(A) + (size_t)m * K + kb + a_c[i] * 4);
            } else {
                aRegF[i] = make_float4(0.f, 0.f, 0.f, 0.f);
                if (arow_ok[i])
                    aRegF[i] = *reinterpret_cast<const float4*>(
                        reinterpret_cast<const float*>(A) + (size_t)m * K + kb + a_c[i] * 4);
            }
        }
    };
    auto loadW = [&](int kb) {
        #pragma unroll
        for (int i = 0; i < WITER; i++) {
            int k = kb + 2 * (k2b + i * KSTEP);
            wReg[i] = make_float2(W[(size_t)k * N + n_w], W[(size_t)(k + 1) * N + n_w]);
        }
    };
    auto commit = [&](int buf) {
        __half* Ab = As + buf * ABUF;
        __half* Wb = Ws + buf * WBUF;
        #pragma unroll
        for (int i = 0; i < 2; i++) {
            uint2 u;
            if (A16) {
                u = aRegH[i];
            } else {
                __half2 p0 = __floats2half2_rn(aRegF[i].x, aRegF[i].y);
                __half2 p1 = __floats2half2_rn(aRegF[i].z, aRegF[i].w);
                u = make_uint2(*reinterpret_cast<unsigned*>(&p0),
                               *reinterpret_cast<unsigned*>(&p1));
            }
            *reinterpret_cast<uint2*>(Ab + a_r[i] * SA + a_c[i] * 4) = u;
        }
        #pragma unroll
        for (int i = 0; i < WITER; i++) {
            int k2 = k2b + i * KSTEP;
            *reinterpret_cast<__half2*>(Wb + n_w * SW + 2 * k2) =
                __floats2half2_rn(wReg[i].x, wReg[i].y);
        }
    };

    // prologue: tile0 -> buf0; prefetch tile1 into regs
    loadA(0); loadW(0);
    commit(0);
    if (BK < K) { loadA(BK); loadW(BK); }

    int cur = 0;
    for (int k0 = 0; k0 < K; k0 += BK) {
        __syncthreads();                       // buf[cur] ready for all
        int kn = k0 + BK;
        if (kn < K) commit(cur ^ 1);           // regs hold tile kn
        int kp = k0 + 2 * BK;
        if (kp < K) { loadA(kp); loadW(kp); }  // 2 tiles ahead

        const __half* Ab = As + cur * ABUF;
        const __half* Wb = Ws + cur * WBUF;
        #pragma unroll
        for (int kk = 0; kk < BK; kk += 16) {
            unsigned a[MT][4];
            #pragma unroll
            for (int mt = 0; mt < MT; mt++) {
                int base = (wm + mt * 16 + g) * SA + kk + tg * 2;
                a[mt][0] = *reinterpret_cast<const unsigned*>(Ab + base);
                a[mt][1] = *reinterpret_cast<const unsigned*>(Ab + base + 8 * SA);
                a[mt][2] = *reinterpret_cast<const unsigned*>(Ab + base + 8);
                a[mt][3] = *reinterpret_cast<const unsigned*>(Ab + base + 8 * SA + 8);
            }
            #pragma unroll
            for (int nt = 0; nt < NT; nt++) {
                int bb = (wn + nt * 8 + g) * SW + kk + tg * 2;
                unsigned b[2];
                b[0] = *reinterpret_cast<const unsigned*>(Wb + bb);
                b[1] = *reinterpret_cast<const unsigned*>(Wb + bb + 8);
                #pragma unroll
                for (int mt = 0; mt < MT; mt++)
                    mma_f16(acc[mt][nt], a[mt], b);
            }
        }
        cur ^= 1;
    }

    #pragma unroll
    for (int mt = 0; mt < MT; mt++) {
        #pragma unroll
        for (int nt = 0; nt < NT; nt++) {
            int row0 = m0 + wm + mt * 16 + g;
            int col = wn + nt * 8 + 2 * tg;
            if (row0 < M)
                *reinterpret_cast<__half2*>(C + (size_t)row0 * N + col) =
                    __floats2half2_rn(acc[mt][nt][0], acc[mt][nt][1]);
            int row1 = row0 + 8;
            if (row1 < M)
                *reinterpret_cast<__half2*>(C + (size_t)row1 * N + col) =
                    __floats2half2_rn(acc[mt][nt][2], acc[mt][nt][3]);
        }
    }
}

// ---------------------------------------------------------------------------
// aggregation: warp per node; fp16 gathers, fp32 accumulate, OutT output
// ---------------------------------------------------------------------------
template <int VEC>
__device__ __forceinline__ void loadh(float* d, const __half* __restrict__ p) {
    if constexpr (VEC == 4) {
        uint2 raw = __ldg(reinterpret_cast<const uint2*>(p));
        float2 a = __half22float2(*reinterpret_cast<const __half2*>(&raw.x));
        float2 b = __half22float2(*reinterpret_cast<const __half2*>(&raw.y));
        d[0] = a.x; d[1] = a.y; d[2] = b.x; d[3] = b.y;
    } else if constexpr (VEC == 2) {
        __half2 h2 = __ldg(reinterpret_cast<const __half2*>(p));
        float2 a = __half22float2(h2);
        d[0] = a.x; d[1] = a.y;
    } else {
        d[0] = __half2float(__ldg(p));
    }
}

template <int F, bool RELU, typename OutT>
__launch_bounds__(256)
__global__ void k_agg(const __half* __restrict__ h, const float* __restrict__ bias,
                      OutT* __restrict__ out) {
    constexpr int VEC = F / 32;
    int node = (blockIdx.x * blockDim.x + threadIdx.x) >> 5;
    int lane = threadIdx.x & 31;
    if (node >= NN) return;

    float acc[VEC];
    {
        float d = g_dis[node];
        float ns = d * d;
        float t[VEC];
        loadh<VEC>(t, h + (size_t)node * F + lane * VEC);
        #pragma unroll
        for (int v = 0; v < VEC; v++) acc[v] = ns * t[v];
    }

    int start = g_off[node];
    int cnt   = g_cnt[node];
    int e = start, end = start + cnt;

    for (; e + 8 <= end; e += 8) {
        int   s[8];
        float nm[8];
        #pragma unroll
        for (int j = 0; j < 8; j++) { s[j] = g_esrc[e + j]; nm[j] = g_enorm[e + j]; }
        float t[8][VEC];
        #pragma unroll
        for (int j = 0; j < 8; j++)
            loadh<VEC>(t[j], h + (size_t)s[j] * F + lane * VEC);
        #pragma unroll
        for (int j = 0; j < 8; j++)
            #pragma unroll
            for (int v = 0; v < VEC; v++) acc[v] += nm[j] * t[j][v];
    }
    for (; e + 4 <= end; e += 4) {
        int   s[4];
        float nm[4];
        #pragma unroll
        for (int j = 0; j < 4; j++) { s[j] = g_esrc[e + j]; nm[j] = g_enorm[e + j]; }
        float t[4][VEC];
        #pragma unroll
        for (int j = 0; j < 4; j++)
            loadh<VEC>(t[j], h + (size_t)s[j] * F + lane * VEC);
        #pragma unroll
        for (int j = 0; j < 4; j++)
            #pragma unroll
            for (int v = 0; v < VEC; v++) acc[v] += nm[j] * t[j][v];
    }
    for (; e < end; e++) {
        int s0 = g_esrc[e];
        float nm = g_enorm[e];
        float t[VEC];
        loadh<VEC>(t, h + (size_t)s0 * F + lane * VEC);
        #pragma unroll
        for (int v = 0; v < VEC; v++) acc[v] += nm * t[v];
    }

    float res[VEC];
    #pragma unroll
    for (int v = 0; v < VEC; v++) {
        float r = acc[v] + bias[lane * VEC + v];
        if (RELU) r = fmaxf(r, 0.0f);
        res[v] = r;
    }

    if constexpr (sizeof(OutT) == 2) {
        __half* op = reinterpret_cast<__half*>(out) + (size_t)node * F + lane * VEC;
        if constexpr (VEC == 4) {
            __half2 p0 = __floats2half2_rn(res[0], res[1]);
            __half2 p1 = __floats2half2_rn(res[2], res[3]);
            *reinterpret_cast<uint2*>(op) =
                make_uint2(*reinterpret_cast<unsigned*>(&p0), *reinterpret_cast<unsigned*>(&p1));
        } else if constexpr (VEC == 2) {
            *reinterpret_cast<__half2*>(op) = __floats2half2_rn(res[0], res[1]);
        } else {
            *op = __float2half_rn(res[0]);
        }
    } else {
        float* op = reinterpret_cast<float*>(out) + (size_t)node * F + lane * VEC;
        if constexpr (VEC == 4)
            *reinterpret_cast<float4*>(op) = make_float4(res[0], res[1], res[2], res[3]);
        else if constexpr (VEC == 2)
            *reinterpret_cast<float2*>(op) = make_float2(res[0], res[1]);
        else
            *op = res[0];
    }
}

// ---------------------------------------------------------------------------
extern "C" void kernel_launch(void* const* d_in, const int* in_sizes, int n_in,
                              void* d_out, int out_size) {
    const float* x  = (const float*)d_in[0];
    const int*   ei = (const int*)d_in[1];
    const float* W1 = (const float*)d_in[2];
    const float* b1 = (const float*)d_in[3];
    const float* W2 = (const float*)d_in[4];
    const float* b2 = (const float*)d_in[5];
    const float* W3 = (const float*)d_in[6];
    const float* b3 = (const float*)d_in[7];

    int M = in_sizes[0] / IN_C;   // 100000
    int E = in_sizes[1] / 2;      // 1600000
    const int* row = ei;          // sources
    const int* col = ei + E;      // targets
    float* out = (float*)d_out;

    __half *gh, *ga;
    cudaGetSymbolAddress((void**)&gh, g_h);
    cudaGetSymbolAddress((void**)&ga, g_a);

    static cudaStream_t s2 = nullptr;
    static cudaEvent_t evFork = nullptr, evJoin = nullptr;
    if (s2 == nullptr) {
        cudaStreamCreateWithFlags(&s2, cudaStreamNonBlocking);
        cudaEventCreateWithFlags(&evFork, cudaEventDisableTiming);
        cudaEventCreateWithFlags(&evJoin, cudaEventDisableTiming);
    }

    int nb1024 = (M + 1023) / 1024;
    int aggBlocks = (M + 7) / 8;
    int gemmBlocks = (M + 63) / 64;

    // ---- fork: CSR preproc on s2, gemm1 on main ----
    cudaEventRecord(evFork, 0);
    cudaStreamWaitEvent(s2, evFork, 0);

    k_zero   <<<(M + 255) / 256, 256, 0, s2>>>(M);
    k_count  <<<(E + 255) / 256, 256, 0, s2>>>(col, E);
    k_scan1  <<<nb1024, 1024, 0, s2>>>(M);
    k_scan2  <<<1, 128, 0, s2>>>(nb1024);
    k_scan3  <<<(M + 255) / 256, 256, 0, s2>>>(M);
    k_scatter<<<(E + 255) / 256, 256, 0, s2>>>(row, col, E);
    cudaEventRecord(evJoin, s2);

    k_gemm<float, H1C, IN_C><<<gemmBlocks, 256>>>(x, W1, gh, M);

    cudaStreamWaitEvent(0, evJoin, 0);

    k_agg<H1C, true, __half><<<aggBlocks, 256>>>(gh, b1, ga);

    k_gemm<__half, H2C, H1C><<<gemmBlocks, 256>>>(ga, W2, gh, M);
    k_agg<H2C, true, __half><<<aggBlocks, 256>>>(gh, b2, ga);

    k_gemm<__half, OUTC, H2C><<<gemmBlocks, 256>>>(ga, W3, gh, M);
    k_agg<OUTC, false, float><<<aggBlocks, 256>>>(gh, b3, out);
}

// round 15
// speedup vs baseline: 1.1415x; 1.0127x over previous
#include <cuda_runtime.h>
#include <cuda_fp16.h>

// ---------------------------------------------------------------------------
// 3-layer GCN. R15: (a) W pre-transposed+pre-converted to fp16 n-major by
// tiny prep kernels -> GEMM tile fill drops from 8xLDG.64+8cvt+8xSTS.32 to
// 2xLDG.128+2xSTS.128 per thread and W L2 traffic halves; (b) k_scan2 launch
// removed (folded into every k_scan3 block); (c) launch order puts gemm1 in
// ncu slot 4. Same rounding everywhere -> rel_err must stay 2.2487e-4.
// ---------------------------------------------------------------------------

#define NN 100000
#define NE 1600000
#define IN_C 256
#define H1C 128
#define H2C 64
#define OUTC 32

__device__ int    g_cnt[NN];
__device__ int    g_cursor[NN];
__device__ int    g_off[NN];
__device__ int    g_bsum[128];
__device__ float  g_dis[NN];
__device__ int    g_esrc[NE];
__device__ float  g_enorm[NE];
__device__ __half g_h[(size_t)NN * 128];   // GEMM outputs (fp16)
__device__ __half g_a[(size_t)NN * 128];   // agg outputs (fp16, layers 1-2)
__device__ __half g_w1t[IN_C * H1C];       // W1^T fp16 [N][K] = [128][256]
__device__ __half g_w2t[H1C * H2C];        // W2^T fp16 [64][128]
__device__ __half g_w3t[H2C * OUTC];       // W3^T fp16 [32][64]

// ---------------------------------------------------------------------------
// W prep: W[K,N] fp32 row-major -> Wt[N,K] fp16
// ---------------------------------------------------------------------------
template <int N, int K>
__global__ void k_wprep(const float* __restrict__ W, __half* __restrict__ Wt) {
    int idx = blockIdx.x * blockDim.x + threadIdx.x;
    if (idx >= N * K) return;
    int n = idx / K, k = idx % K;                  // writes coalesced over k
    Wt[idx] = __float2half_rn(W[(size_t)k * N + n]);
}

// ---------------------------------------------------------------------------
// graph preprocessing
// ---------------------------------------------------------------------------
__global__ void k_zero(int n) {
    int i = blockIdx.x * blockDim.x + threadIdx.x;
    if (i < n) g_cnt[i] = 0;
}
__global__ void k_count(const int* __restrict__ col, int e_cnt) {
    int e = blockIdx.x * blockDim.x + threadIdx.x;
    if (e < e_cnt) atomicAdd(&g_cnt[col[e]], 1);
}
__global__ void k_scan1(int n) {
    __shared__ int s[1024];
    int i = blockIdx.x * 1024 + threadIdx.x;
    int v = (i < n) ? g_cnt[i] : 0;
    if (i < n) g_dis[i] = rsqrtf((float)v + 1.0f);
    s[threadIdx.x] = v;
    __syncthreads();
    #pragma unroll
    for (int off = 1; off < 1024; off <<= 1) {
        int t = (threadIdx.x >= off) ? s[threadIdx.x - off] : 0;
        __syncthreads();
        s[threadIdx.x] += t;
        __syncthreads();
    }
    if (i < n) g_off[i] = s[threadIdx.x];
    if (threadIdx.x == 1023) g_bsum[blockIdx.x] = s[1023];
}
// scan3 with the 98-element block-sum scan folded in (per block, trivial)
__global__ void k_scan3(int n, int nb) {
    __shared__ int pref[128];
    int t = threadIdx.x;
    int v = (t < 128 && t < nb) ? g_bsum[t] : 0;
    if (t < 128) pref[t] = v;
    __syncthreads();
    #pragma unroll
    for (int off = 1; off < 128; off <<= 1) {
        int u = (t < 128 && t >= off) ? pref[t - off] : 0;
        __syncthreads();
        if (t < 128) pref[t] += u;
        __syncthreads();
    }
    int i = blockIdx.x * blockDim.x + t;
    if (i < n) {
        int b = i >> 10;
        int boff = pref[b] - g_bsum[b];            // exclusive
        int off = g_off[i] - g_cnt[i] + boff;
        g_off[i] = off;
        g_cursor[i] = off;
    }
}
__global__ void k_scatter(const int* __restrict__ row, const int* __restrict__ col, int e_cnt) {
    int e = blockIdx.x * blockDim.x + threadIdx.x;
    if (e >= e_cnt) return;
    int r = row[e], c = col[e];
    int pos = atomicAdd(&g_cursor[c], 1);
    g_esrc[pos]  = r;
    g_enorm[pos] = g_dis[r] * g_dis[c];
}

// ---------------------------------------------------------------------------
// fp16 GEMM, double-buffered, 2-tile lookahead, pre-transposed fp16 W
// ---------------------------------------------------------------------------
__device__ __forceinline__ void mma_f16(float* c, const unsigned* a, const unsigned* b) {
    asm volatile(
        "mma.sync.aligned.m16n8k16.row.col.f32.f16.f16.f32 "
        "{%0,%1,%2,%3},{%4,%5,%6,%7},{%8,%9},{%0,%1,%2,%3};"
        : "+f"(c[0]), "+f"(c[1]), "+f"(c[2]), "+f"(c[3])
        : "r"(a[0]), "r"(a[1]), "r"(a[2]), "r"(a[3]), "r"(b[0]), "r"(b[1]));
}

template <typename AT, int N, int K>
__launch_bounds__(256, 2)
__global__ void k_gemm(const AT* __restrict__ A, const __half* __restrict__ Wt,
                       __half* __restrict__ C, int M) {
    constexpr bool A16 = (sizeof(AT) == 2);
    constexpr int BM = 64, BK = 32;
    constexpr int SA = BK + 8;          // 40 halves
    constexpr int SW = BK + 8;          // 40 halves (16B-aligned rows, conflict-free frags)
    constexpr int WM = 32;
    constexpr int WN = N / 4;
    constexpr int MT = 2;
    constexpr int NT = WN / 8;
    constexpr int ABUF = BM * SA;
    constexpr int WBUF = N * SW;
    constexpr int WUNITS = N * 4;       // uint4 units per W tile (N rows x 4 segs)
    constexpr int WLOC = (WUNITS + 255) / 256;

    __shared__ __align__(16) __half As[2 * ABUF];
    __shared__ __align__(16) __half Ws[2 * WBUF];

    int tid = threadIdx.x;
    int lane = tid & 31, warp = tid >> 5;
    int wm = (warp & 1) * WM;
    int wn = (warp >> 1) * WN;
    int m0 = blockIdx.x * BM;
    int g = lane >> 2, tg = lane & 3;

    float acc[MT][NT][4] = {};

    int a_r[2], a_c[2];
    #pragma unroll
    for (int i = 0; i < 2; i++) {
        int idx = tid + i * 256;
        a_r[i] = idx >> 3;
        a_c[i] = idx & 7;
    }
    bool arow_ok[2];
    #pragma unroll
    for (int i = 0; i < 2; i++) arow_ok[i] = (m0 + a_r[i]) < M;

    float4 aRegF[2];
    uint2  aRegH[2];
    uint4  wReg[WLOC];

    auto loadA = [&](int kb) {
        #pragma unroll
        for (int i = 0; i < 2; i++) {
            int m = m0 + a_r[i];
            if (A16) {
                aRegH[i] = make_uint2(0u, 0u);
                if (arow_ok[i])
                    aRegH[i] = *reinterpret_cast<const uint2*>(
                        reinterpret_cast<const __half*>(A) + (size_t)m * K + kb + a_c[i] * 4);
            } else {
                aRegF[i] = make_float4(0.f, 0.f, 0.f, 0.f);
                if (arow_ok[i])
                    aRegF[i] = *reinterpret_cast<const float4*>(
                        reinterpret_cast<const float*>(A) + (size_t)m * K + kb + a_c[i] * 4);
            }
        }
    };
    auto loadW = [&](int kb) {
        #pragma unroll
        for (int i = 0; i < WLOC; i++) {
            int u = tid + i * 256;
            if (WUNITS >= 256 || u < WUNITS) {
                int n = u >> 2, seg = u & 3;
                wReg[i] = *reinterpret_cast<const uint4*>(Wt + (size_t)n * K + kb + seg * 8);
            }
        }
    };
    auto commit = [&](int buf) {
        __half* Ab = As + buf * ABUF;
        __half* Wb = Ws + buf * WBUF;
        #pragma unroll
        for (int i = 0; i < 2; i++) {
            uint2 u;
            if (A16) {
                u = aRegH[i];
            } else {
                __half2 p0 = __floats2half2_rn(aRegF[i].x, aRegF[i].y);
                __half2 p1 = __floats2half2_rn(aRegF[i].z, aRegF[i].w);
                u = make_uint2(*reinterpret_cast<unsigned*>(&p0),
                               *reinterpret_cast<unsigned*>(&p1));
            }
            *reinterpret_cast<uint2*>(Ab + a_r[i] * SA + a_c[i] * 4) = u;
        }
        #pragma unroll
        for (int i = 0; i < WLOC; i++) {
            int u = tid + i * 256;
            if (WUNITS >= 256 || u < WUNITS) {
                int n = u >> 2, seg = u & 3;
                *reinterpret_cast<uint4*>(Wb + n * SW + seg * 8) = wReg[i];
            }
        }
    };

    // prologue
    loadA(0); loadW(0);
    commit(0);
    if (BK < K) { loadA(BK); loadW(BK); }

    int cur = 0;
    for (int k0 = 0; k0 < K; k0 += BK) {
        __syncthreads();
        int kn = k0 + BK;
        if (kn < K) commit(cur ^ 1);
        int kp = k0 + 2 * BK;
        if (kp < K) { loadA(kp); loadW(kp); }

        const __half* Ab = As + cur * ABUF;
        const __half* Wb = Ws + cur * WBUF;
        #pragma unroll
        for (int kk = 0; kk < BK; kk += 16) {
            unsigned a[MT][4];
            #pragma unroll
            for (int mt = 0; mt < MT; mt++) {
                int base = (wm + mt * 16 + g) * SA + kk + tg * 2;
                a[mt][0] = *reinterpret_cast<const unsigned*>(Ab + base);
                a[mt][1] = *reinterpret_cast<const unsigned*>(Ab + base + 8 * SA);
                a[mt][2] = *reinterpret_cast<const unsigned*>(Ab + base + 8);
                a[mt][3] = *reinterpret_cast<const unsigned*>(Ab + base + 8 * SA + 8);
            }
            #pragma unroll
            for (int nt = 0; nt < NT; nt++) {
                int bb = (wn + nt * 8 + g) * SW + kk + tg * 2;
                unsigned b[2];
                b[0] = *reinterpret_cast<const unsigned*>(Wb + bb);
                b[1] = *reinterpret_cast<const unsigned*>(Wb + bb + 8);
                #pragma unroll
                for (int mt = 0; mt < MT; mt++)
                    mma_f16(acc[mt][nt], a[mt], b);
            }
        }
        cur ^= 1;
    }

    #pragma unroll
    for (int mt = 0; mt < MT; mt++) {
        #pragma unroll
        for (int nt = 0; nt < NT; nt++) {
            int row0 = m0 + wm + mt * 16 + g;
            int col = wn + nt * 8 + 2 * tg;
            if (row0 < M)
                *reinterpret_cast<__half2*>(C + (size_t)row0 * N + col) =
                    __floats2half2_rn(acc[mt][nt][0], acc[mt][nt][1]);
            int row1 = row0 + 8;
            if (row1 < M)
                *reinterpret_cast<__half2*>(C + (size_t)row1 * N + col) =
                    __floats2half2_rn(acc[mt][nt][2], acc[mt][nt][3]);
        }
    }
}

// ---------------------------------------------------------------------------
// aggregation: warp per node; fp16 gathers, fp32 accumulate, OutT output
// ---------------------------------------------------------------------------
template <int VEC>
__device__ __forceinline__ void loadh(float* d, const __half* __restrict__ p) {
    if constexpr (VEC == 4) {
        uint2 raw = __ldg(reinterpret_cast<const uint2*>(p));
        float2 a = __half22float2(*reinterpret_cast<const __half2*>(&raw.x));
        float2 b = __half22float2(*reinterpret_cast<const __half2*>(&raw.y));
        d[0] = a.x; d[1] = a.y; d[2] = b.x; d[3] = b.y;
    } else if constexpr (VEC == 2) {
        __half2 h2 = __ldg(reinterpret_cast<const __half2*>(p));
        float2 a = __half22float2(h2);
        d[0] = a.x; d[1] = a.y;
    } else {
        d[0] = __half2float(__ldg(p));
    }
}

template <int F, bool RELU, typename OutT>
__launch_bounds__(256)
__global__ void k_agg(const __half* __restrict__ h, const float* __restrict__ bias,
                      OutT* __restrict__ out) {
    constexpr int VEC = F / 32;
    int node = (blockIdx.x * blockDim.x + threadIdx.x) >> 5;
    int lane = threadIdx.x & 31;
    if (node >= NN) return;

    float acc[VEC];
    {
        float d = g_dis[node];
        float ns = d * d;
        float t[VEC];
        loadh<VEC>(t, h + (size_t)node * F + lane * VEC);
        #pragma unroll
        for (int v = 0; v < VEC; v++) acc[v] = ns * t[v];
    }

    int start = g_off[node];
    int cnt   = g_cnt[node];
    int e = start, end = start + cnt;

    for (; e + 8 <= end; e += 8) {
        int   s[8];
        float nm[8];
        #pragma unroll
        for (int j = 0; j < 8; j++) { s[j] = g_esrc[e + j]; nm[j] = g_enorm[e + j]; }
        float t[8][VEC];
        #pragma unroll
        for (int j = 0; j < 8; j++)
            loadh<VEC>(t[j], h + (size_t)s[j] * F + lane * VEC);
        #pragma unroll
        for (int j = 0; j < 8; j++)
            #pragma unroll
            for (int v = 0; v < VEC; v++) acc[v] += nm[j] * t[j][v];
    }
    for (; e + 4 <= end; e += 4) {
        int   s[4];
        float nm[4];
        #pragma unroll
        for (int j = 0; j < 4; j++) { s[j] = g_esrc[e + j]; nm[j] = g_enorm[e + j]; }
        float t[4][VEC];
        #pragma unroll
        for (int j = 0; j < 4; j++)
            loadh<VEC>(t[j], h + (size_t)s[j] * F + lane * VEC);
        #pragma unroll
        for (int j = 0; j < 4; j++)
            #pragma unroll
            for (int v = 0; v < VEC; v++) acc[v] += nm[j] * t[j][v];
    }
    for (; e < end; e++) {
        int s0 = g_esrc[e];
        float nm = g_enorm[e];
        float t[VEC];
        loadh<VEC>(t, h + (size_t)s0 * F + lane * VEC);
        #pragma unroll
        for (int v = 0; v < VEC; v++) acc[v] += nm * t[v];
    }

    float res[VEC];
    #pragma unroll
    for (int v = 0; v < VEC; v++) {
        float r = acc[v] + bias[lane * VEC + v];
        if (RELU) r = fmaxf(r, 0.0f);
        res[v] = r;
    }

    if constexpr (sizeof(OutT) == 2) {
        __half* op = reinterpret_cast<__half*>(out) + (size_t)node * F + lane * VEC;
        if constexpr (VEC == 4) {
            __half2 p0 = __floats2half2_rn(res[0], res[1]);
            __half2 p1 = __floats2half2_rn(res[2], res[3]);
            *reinterpret_cast<uint2*>(op) =
                make_uint2(*reinterpret_cast<unsigned*>(&p0), *reinterpret_cast<unsigned*>(&p1));
        } else if constexpr (VEC == 2) {
            *reinterpret_cast<__half2*>(op) = __floats2half2_rn(res[0], res[1]);
        } else {
            *op = __float2half_rn(res[0]);
        }
    } else {
        float* op = reinterpret_cast<float*>(out) + (size_t)node * F + lane * VEC;
        if constexpr (VEC == 4)
            *reinterpret_cast<float4*>(op) = make_float4(res[0], res[1], res[2], res[3]);
        else if constexpr (VEC == 2)
            *reinterpret_cast<float2*>(op) = make_float2(res[0], res[1]);
        else
            *op = res[0];
    }
}

// ---------------------------------------------------------------------------
extern "C" void kernel_launch(void* const* d_in, const int* in_sizes, int n_in,
                              void* d_out, int out_size) {
    const float* x  = (const float*)d_in[0];
    const int*   ei = (const int*)d_in[1];
    const float* W1 = (const float*)d_in[2];
    const float* b1 = (const float*)d_in[3];
    const float* W2 = (const float*)d_in[4];
    const float* b2 = (const float*)d_in[5];
    const float* W3 = (const float*)d_in[6];
    const float* b3 = (const float*)d_in[7];

    int M = in_sizes[0] / IN_C;   // 100000
    int E = in_sizes[1] / 2;      // 1600000
    const int* row = ei;          // sources
    const int* col = ei + E;      // targets
    float* out = (float*)d_out;

    __half *gh, *ga, *w1t, *w2t, *w3t;
    cudaGetSymbolAddress((void**)&gh, g_h);
    cudaGetSymbolAddress((void**)&ga, g_a);
    cudaGetSymbolAddress((void**)&w1t, g_w1t);
    cudaGetSymbolAddress((void**)&w2t, g_w2t);
    cudaGetSymbolAddress((void**)&w3t, g_w3t);

    static cudaStream_t s2 = nullptr;
    static cudaEvent_t evFork = nullptr, evJoin = nullptr;
    if (s2 == nullptr) {
        cudaStreamCreateWithFlags(&s2, cudaStreamNonBlocking);
        cudaEventCreateWithFlags(&evFork, cudaEventDisableTiming);
        cudaEventCreateWithFlags(&evJoin, cudaEventDisableTiming);
    }

    int nb1024 = (M + 1023) / 1024;
    int aggBlocks = (M + 7) / 8;
    int gemmBlocks = (M + 63) / 64;

    // ---- fork ----
    cudaEventRecord(evFork, 0);
    cudaStreamWaitEvent(s2, evFork, 0);

    // launch-call order puts gemm1 in ncu slot 4
    k_wprep<H1C, IN_C><<<(IN_C * H1C + 255) / 256, 256>>>(W1, w1t);         // 1 (main)
    k_zero <<<(M + 255) / 256, 256, 0, s2>>>(M);                            // 2
    k_count<<<(E + 255) / 256, 256, 0, s2>>>(col, E);                       // 3
    k_gemm<float, H1C, IN_C><<<gemmBlocks, 256>>>(x, w1t, gh, M);           // 4 <- profiled
    k_scan1  <<<nb1024, 1024, 0, s2>>>(M);                                  // 5
    k_scan3  <<<(M + 255) / 256, 256, 0, s2>>>(M, nb1024);                  // 6
    k_scatter<<<(E + 255) / 256, 256, 0, s2>>>(row, col, E);                // 7
    k_wprep<H2C, H1C> <<<(H1C * H2C + 255) / 256, 256, 0, s2>>>(W2, w2t);   // 8
    k_wprep<OUTC, H2C><<<(H2C * OUTC + 255) / 256, 256, 0, s2>>>(W3, w3t);  // 9
    cudaEventRecord(evJoin, s2);

    cudaStreamWaitEvent(0, evJoin, 0);

    k_agg<H1C, true, __half><<<aggBlocks, 256>>>(gh, b1, ga);

    k_gemm<__half, H2C, H1C><<<gemmBlocks, 256>>>(ga, w2t, gh, M);
    k_agg<H2C, true, __half><<<aggBlocks, 256>>>(gh, b2, ga);

    k_gemm<__half, OUTC, H2C><<<gemmBlocks, 256>>>(ga, w3t, gh, M);
    k_agg<OUTC, false, float><<<aggBlocks, 256>>>(gh, b3, out);
}